// round 15
// baseline (speedup 1.0000x reference)
#include <cuda_runtime.h>
#include <cuda_bf16.h>
#include <cstdint>

#define BB 32
#define KKS 10
#define TT 128
#define LLS 128
#define DD 1024
#define NTAG 32
#define SS (KKS*LLS)     // 1280
#define CH 20            // chunks of 64 support rows
#define CROWS 64

typedef unsigned long long ull;

// ---- dynamic smem layout for gemm (1024-aligned tiles, 48KB exactly) ----
#define OFF_AHI   0
#define OFF_ALO   16384
#define OFF_BHI   32768
#define OFF_BLO   40960
#define GEMM_SMEM 49152

#define NMEAN  4096      // mean blocks in F1

// ---------------- scratch (device globals; no allocation) ----------------
__device__ uint4  g_ahi[BB*TT*DD/8];           // test_mean hi bf16
__device__ uint4  g_alo[BB*TT*DD/8];           // test_mean lo bf16
__device__ int    g_list[BB*NTAG*256];
__device__ int    g_cnt[BB*NTAG];
__device__ float2 g_cmin[BB*TT*CH];

// ---------------- helpers ----------------
__device__ __forceinline__ uint32_t smem_u32(const void* p){
    uint32_t a;
    asm("{ .reg .u64 t; cvta.to.shared.u64 t, %1; cvt.u32.u64 %0, t; }" : "=r"(a) : "l"(p));
    return a;
}
__device__ __forceinline__ float4 add4(float4 a, float4 b){
    return make_float4(a.x+b.x, a.y+b.y, a.z+b.z, a.w+b.w);
}
__device__ __forceinline__ void bf16_split4(float4 v, uint32_t& h01, uint32_t& h23,
                                            uint32_t& l01, uint32_t& l23){
    asm("cvt.rn.bf16x2.f32 %0, %1, %2;" : "=r"(h01) : "f"(v.y), "f"(v.x));
    asm("cvt.rn.bf16x2.f32 %0, %1, %2;" : "=r"(h23) : "f"(v.w), "f"(v.z));
    float hx = __uint_as_float(h01<<16), hy = __uint_as_float(h01 & 0xffff0000u);
    float hz = __uint_as_float(h23<<16), hw = __uint_as_float(h23 & 0xffff0000u);
    asm("cvt.rn.bf16x2.f32 %0, %1, %2;" : "=r"(l01) : "f"(v.y-hy), "f"(v.x-hx));
    asm("cvt.rn.bf16x2.f32 %0, %1, %2;" : "=r"(l23) : "f"(v.w-hw), "f"(v.z-hz));
}
__device__ __forceinline__ void ldm_x4(uint32_t r[4], uint32_t addr){
    asm volatile("ldmatrix.sync.aligned.m8n8.x4.shared.b16 {%0,%1,%2,%3}, [%4];"
        : "=r"(r[0]),"=r"(r[1]),"=r"(r[2]),"=r"(r[3]) : "r"(addr));
}
__device__ __forceinline__ void mma_bf16(float c[4], const uint32_t a[4],
                                         uint32_t b0, uint32_t b1){
    asm volatile("mma.sync.aligned.m16n8k16.row.col.f32.bf16.bf16.f32 "
        "{%0,%1,%2,%3}, {%4,%5,%6,%7}, {%8,%9}, {%0,%1,%2,%3};"
        : "+f"(c[0]),"+f"(c[1]),"+f"(c[2]),"+f"(c[3])
        : "r"(a[0]),"r"(a[1]),"r"(a[2]),"r"(a[3]), "r"(b0),"r"(b1));
}
__device__ __forceinline__ uint32_t sw128(uint32_t off){ return off ^ ((off>>3)&0x70); }

// ================= F1: mean blocks + labels blocks =================
__global__ __launch_bounds__(256,4) void k_f1(const float* __restrict__ x,
                                              const float* __restrict__ tgt){
    __shared__ int lab[SS];
    const int gx = blockIdx.x, tid = threadIdx.x;
    if (gx < NMEAN){
        int idx = gx*256 + tid;
        int b   = idx / (TT*DD/4);
        int rem = idx - b*(TT*DD/4);
        const float4* p = (const float4*)x + (size_t)b*KKS*(TT*DD/4) + rem;
        float4 v[KKS];
#pragma unroll
        for (int k=0;k<KKS;k++) v[k] = p[(size_t)k*(TT*DD/4)];
        float4 s0 = add4(v[0], v[1]);
        float4 s1 = add4(v[2], v[3]);
        float4 s2 = add4(v[4], v[5]);
        float4 s3 = add4(v[6], v[7]);
        float4 s4 = add4(v[8], v[9]);
        float4 a  = add4(add4(add4(s0,s1), add4(s2,s3)), s4);
        const float s = 1.0f/(float)KKS;
        a.x*=s; a.y*=s; a.z*=s; a.w*=s;
        uint32_t h01,h23,l01,l23;
        bf16_split4(a, h01,h23,l01,l23);
        ((uint2*)g_ahi)[idx] = make_uint2(h01,h23);
        ((uint2*)g_alo)[idx] = make_uint2(l01,l23);
    } else {
        int b = gx - NMEAN;
        for (int s = tid; s < SS; s += 256){
            const float* row = tgt + ((size_t)b*SS + s)*NTAG;
            float bv = row[0]; int bi = 0;
#pragma unroll
            for (int n=1;n<NTAG;n++){ float v=row[n]; if (v>bv){bv=v;bi=n;} }
            lab[s] = bi;
        }
        __syncthreads();
        int w = tid >> 5, lane = tid & 31;
        for (int n = w; n < NTAG; n += 8){
            int c = 0;
            int* lst = g_list + ((size_t)b*NTAG + n)*256;
            for (int s0 = 0; s0 < SS; s0 += 32){
                int s = s0 + lane;
                bool m = (lab[s] == n);
                unsigned bal = __ballot_sync(0xffffffffu, m);
                if (m && c + __popc(bal & ((1u<<lane)-1u)) < 256)
                    lst[c + __popc(bal & ((1u<<lane)-1u))] = s;
                c += __popc(bal);
            }
            if (lane == 0) g_cnt[b*NTAG + n] = (c < 256) ? c : 256;
        }
    }
}

// ---------------- prototypes: gather-sum / (count+1e-4), 8-wide MLP ----------------
__global__ __launch_bounds__(256) void k_proto(const float* __restrict__ sup,
                                               float* __restrict__ proto){
    int b = blockIdx.x, n = blockIdx.y, tid = threadIdx.x;
    __shared__ int sl[256];
    int cnt = g_cnt[b*NTAG + n];
    const int* lst = g_list + ((size_t)b*NTAG + n)*256;
    sl[tid] = (tid < cnt) ? lst[tid] : 0;
    __syncthreads();
    float4 acc = make_float4(0.f,0.f,0.f,0.f);
    const float4* base = (const float4*)(sup + (size_t)b*SS*DD) + tid;
    int jj = 0;
    for (; jj+8 <= cnt; jj += 8){
        float4 v[8];
#pragma unroll
        for (int q=0;q<8;q++) v[q] = base[(size_t)sl[jj+q]*(DD/4)];
        float4 p0 = add4(v[0],v[1]), p1 = add4(v[2],v[3]);
        float4 p2 = add4(v[4],v[5]), p3 = add4(v[6],v[7]);
        acc = add4(acc, add4(add4(p0,p1), add4(p2,p3)));
    }
    for (; jj < cnt; jj++)
        acc = add4(acc, base[(size_t)sl[jj]*(DD/4)]);
    float inv = 1.0f/((float)cnt + 1e-4f);
    acc.x*=inv; acc.y*=inv; acc.z*=inv; acc.w*=inv;
    ((float4*)(proto + ((size_t)b*NTAG + n)*DD))[tid] = acc;
}

// ---------------- HMMA bf16x3 GEMM (128 x 64 x 1024) + argmin (R14 exact) ----------------
__global__ __launch_bounds__(256,2) void k_gemm(const float* __restrict__ sup){
    extern __shared__ char smem[];
    const uint32_t sb = smem_u32(smem);
    const int ch = blockIdx.x, b = blockIdx.y;
    const int tid = threadIdx.x;
    const int lane = tid & 31, wid = tid >> 5;
    const int warp_m = wid & 3, warp_n = wid >> 2;

    const uint4*  A4h = g_ahi + (size_t)b*(TT*DD/8);
    const uint4*  A4l = g_alo + (size_t)b*(TT*DD/8);
    const float4* B4  = (const float4*)(sup + ((size_t)b*SS + (size_t)ch*CROWS)*DD);

    int amq[4], ajq[4], brq[4], bcq[4];
    uint32_t asw[4], bsw[4];
#pragma unroll
    for (int q=0;q<4;q++){
        int jj = tid + q*256;
        amq[q] = jj >> 3;  ajq[q] = jj & 7;
        asw[q] = sw128((uint32_t)(amq[q]*128 + ajq[q]*16));
        brq[q] = jj >> 4;  bcq[q] = jj & 15;
        bsw[q] = sw128((uint32_t)(brq[q]*128 + bcq[q]*8));
    }

    float acc[2][4][4];
#pragma unroll
    for (int mt=0;mt<2;mt++)
#pragma unroll
        for (int nn=0;nn<4;nn++)
#pragma unroll
            for (int e=0;e<4;e++) acc[mt][nn][e]=0.f;
    float nrm[4] = {0.f,0.f,0.f,0.f};

    const int a_row = (lane & 15);
    const int a_kb  = (lane >> 4) * 16;
    const int b_row = (lane & 7) + ((lane >> 4) << 3);
    const int b_kb  = ((lane >> 3) & 1) * 16;

    for (int kt = 0; kt < 16; kt++){
        __syncthreads();
        uint4 rAh[4], rAl[4]; float4 rB[4];
#pragma unroll
        for (int q=0;q<4;q++){
            rAh[q] = A4h[amq[q]*128 + kt*8 + ajq[q]];
            rAl[q] = A4l[amq[q]*128 + kt*8 + ajq[q]];
            rB[q]  = B4[(size_t)brq[q]*256 + kt*16 + bcq[q]];
        }
#pragma unroll
        for (int q=0;q<4;q++){
            *(uint4*)(smem + OFF_AHI + asw[q]) = rAh[q];
            *(uint4*)(smem + OFF_ALO + asw[q]) = rAl[q];
            float4 v = rB[q];
            nrm[q] += v.x*v.x + v.y*v.y + v.z*v.z + v.w*v.w;
            uint32_t h01,h23,l01,l23;
            bf16_split4(v, h01,h23,l01,l23);
            *(uint2*)(smem + OFF_BHI + bsw[q]) = make_uint2(h01,h23);
            *(uint2*)(smem + OFF_BLO + bsw[q]) = make_uint2(l01,l23);
        }
        __syncthreads();
#pragma unroll
        for (int ks=0; ks<4; ks++){
            uint32_t ah[2][4], al[2][4], bh[2][4], bl[2][4];
#pragma unroll
            for (int mt=0;mt<2;mt++){
                uint32_t off = sw128((uint32_t)((warp_m*32 + mt*16 + a_row)*128 + ks*32 + a_kb));
                ldm_x4(ah[mt], sb + OFF_AHI + off);
                ldm_x4(al[mt], sb + OFF_ALO + off);
            }
#pragma unroll
            for (int p=0;p<2;p++){
                uint32_t off = sw128((uint32_t)((warp_n*32 + p*16 + b_row)*128 + ks*32 + b_kb));
                ldm_x4(bh[p], sb + OFF_BHI + off);
                ldm_x4(bl[p], sb + OFF_BLO + off);
            }
#pragma unroll
            for (int mt=0;mt<2;mt++)
#pragma unroll
                for (int nn=0;nn<4;nn++){
                    const int p = nn>>1, h = (nn&1)*2;
                    mma_bf16(acc[mt][nn], ah[mt], bh[p][h], bh[p][h+1]);
                    mma_bf16(acc[mt][nn], ah[mt], bl[p][h], bl[p][h+1]);
                    mma_bf16(acc[mt][nn], al[mt], bh[p][h], bh[p][h+1]);
                }
        }
    }
    __syncthreads();

    float*  snorm_s = (float*)(smem);
    float2* rmin_s  = (float2*)(smem + 256);

#pragma unroll
    for (int q=0;q<4;q++){
        float v = nrm[q];
        v += __shfl_xor_sync(0xffffffffu, v, 8, 16);
        v += __shfl_xor_sync(0xffffffffu, v, 4, 16);
        v += __shfl_xor_sync(0xffffffffu, v, 2, 16);
        v += __shfl_xor_sync(0xffffffffu, v, 1, 16);
        if ((tid & 15) == 0) snorm_s[(tid>>4) + q*16] = v;
    }
    __syncthreads();

#pragma unroll
    for (int mt=0;mt<2;mt++){
#pragma unroll
        for (int rh=0;rh<2;rh++){
            int m = warp_m*32 + mt*16 + (lane>>2) + rh*8;
            float bv = 3.4e38f; int bi = 1<<30;
#pragma unroll
            for (int nn=0;nn<4;nn++){
#pragma unroll
                for (int e=0;e<2;e++){
                    int n = warp_n*32 + nn*8 + 2*(lane&3) + e;
                    float s = snorm_s[n] - 2.f*acc[mt][nn][rh*2+e];
                    if (s < bv || (s==bv && n < bi)){ bv=s; bi=n; }
                }
            }
#pragma unroll
            for (int o=2;o;o>>=1){
                float ov = __shfl_down_sync(0xffffffffu, bv, o, 4);
                int   oi = __shfl_down_sync(0xffffffffu, bi, o, 4);
                if (ov < bv || (ov==bv && oi<bi)){ bv=ov; bi=oi; }
            }
            if ((lane&3)==0) rmin_s[m*2 + warp_n] = make_float2(bv, __int_as_float(bi));
        }
    }
    __syncthreads();
    if (tid < TT){
        float2 v0 = rmin_s[tid*2 + 0], v1 = rmin_s[tid*2 + 1];
        float bv = v0.x; int bi = __float_as_int(v0.y);
        if (v1.x < bv){ bv = v1.x; bi = __float_as_int(v1.y); }
        g_cmin[((size_t)b*TT + tid)*CH + ch] = make_float2(bv, __int_as_float(ch*CROWS + bi));
    }
}

// ------- k_final: grid (B,2); 64 rows x 32 tags; 8 tags/thread; coalesced loaders -------
__global__ __launch_bounds__(256) void k_final(const float* __restrict__ tgt,
                                               const float* __restrict__ proto,
                                               float* __restrict__ outs){
    __shared__ float As[64][65];   // [k][row], 64 rows; stride 65 (2-way store conflicts max)
    __shared__ float Bs[64][36];   // [k][tag]; 144B stride keeps LDS.128 16B-aligned
    __shared__ int   snn[64];
    int b = blockIdx.x, seg = blockIdx.y, tid = threadIdx.x;
    const int row = tid & 63, tg = tid >> 6;   // 64 rows x 4 tag-octets

    // fused nn reduction over 20 chunks (threads 0..63)
    if (tid < 64){
        const float2* e = &g_cmin[((size_t)b*TT + seg*64 + tid)*CH];
        float2 v0 = e[0];
        float bv = v0.x; int bi = __float_as_int(v0.y);
#pragma unroll
        for (int c=1;c<CH;c++){
            float2 v = e[c];
            if (v.x < bv){ bv = v.x; bi = __float_as_int(v.y); }
        }
        snn[tid] = bi;
    }

    // A from bf16 hi/lo (exact-to-1e-5 reconstruct); coalesced k-contiguous loads
    const uint2* Ah = (const uint2*)g_ahi + ((size_t)(b*TT + seg*64))*(DD/4);
    const uint2* Al = (const uint2*)g_alo + ((size_t)(b*TT + seg*64))*(DD/4);
    const float4* Pb4 = (const float4*)(proto + (size_t)b*NTAG*DD);

    // loader geometry: A 64 rows x 16 k4-groups (4/thread); B 32 rows x 16 (2/thread)
    int arow[4], ak4[4], brow[2], bk4[2];
#pragma unroll
    for (int q=0;q<4;q++){ int jj = tid + q*256; arow[q]=jj>>4; ak4[q]=jj&15; }
#pragma unroll
    for (int q=0;q<2;q++){ int jj = tid + q*256; brow[q]=jj>>4; bk4[q]=jj&15; }

    // preload kt=0
    uint2 ah[4], al[4]; float4 vb[2];
#pragma unroll
    for (int q=0;q<4;q++){
        ah[q] = Ah[(size_t)arow[q]*(DD/4) + ak4[q]];
        al[q] = Al[(size_t)arow[q]*(DD/4) + ak4[q]];
    }
#pragma unroll
    for (int q=0;q<2;q++) vb[q] = Pb4[(size_t)brow[q]*(DD/4) + bk4[q]];

    ull acc[4];
#pragma unroll
    for (int i=0;i<4;i++) acc[i]=0ull;

    for (int kt=0; kt<16; kt++){
        __syncthreads();
#pragma unroll
        for (int q=0;q<4;q++){
            uint32_t h01=ah[q].x, h23=ah[q].y, l01=al[q].x, l23=al[q].y;
            int k0 = ak4[q]*4, r = arow[q];
            As[k0+0][r] = __uint_as_float(h01<<16)          + __uint_as_float(l01<<16);
            As[k0+1][r] = __uint_as_float(h01&0xffff0000u)  + __uint_as_float(l01&0xffff0000u);
            As[k0+2][r] = __uint_as_float(h23<<16)          + __uint_as_float(l23<<16);
            As[k0+3][r] = __uint_as_float(h23&0xffff0000u)  + __uint_as_float(l23&0xffff0000u);
        }
#pragma unroll
        for (int q=0;q<2;q++){
            int k0 = bk4[q]*4, r = brow[q];
            Bs[k0+0][r]=vb[q].x; Bs[k0+1][r]=vb[q].y; Bs[k0+2][r]=vb[q].z; Bs[k0+3][r]=vb[q].w;
        }
        __syncthreads();
        if (kt < 15){
            const int off = (kt+1)*16;
#pragma unroll
            for (int q=0;q<4;q++){
                ah[q] = Ah[(size_t)arow[q]*(DD/4) + off + ak4[q]];
                al[q] = Al[(size_t)arow[q]*(DD/4) + off + ak4[q]];
            }
#pragma unroll
            for (int q=0;q<2;q++) vb[q] = Pb4[(size_t)brow[q]*(DD/4) + off + bk4[q]];
        }
#pragma unroll
        for (int kk=0;kk<64;kk++){
            float a = As[kk][row];
            const ull* bp = (const ull*)&Bs[kk][tg*8];
            ull b0 = bp[0], b1 = bp[1], b2 = bp[2], b3 = bp[3];
            ull aa;
            asm("mov.b64 %0, {%1, %1};" : "=l"(aa) : "f"(a));
            asm("fma.rn.f32x2 %0, %1, %2, %0;" : "+l"(acc[0]) : "l"(aa), "l"(b0));
            asm("fma.rn.f32x2 %0, %1, %2, %0;" : "+l"(acc[1]) : "l"(aa), "l"(b1));
            asm("fma.rn.f32x2 %0, %1, %2, %0;" : "+l"(acc[2]) : "l"(aa), "l"(b2));
            asm("fma.rn.f32x2 %0, %1, %2, %0;" : "+l"(acc[3]) : "l"(aa), "l"(b3));
        }
    }
    __syncthreads();

    int nn = snn[row];
    float2 d0 = *(float2*)&acc[0], d1 = *(float2*)&acc[1];
    float2 d2 = *(float2*)&acc[2], d3 = *(float2*)&acc[3];
    const float4* tp = (const float4*)(tgt + ((size_t)b*SS + nn)*NTAG + tg*8);
    float4 t0 = tp[0], t1 = tp[1];
    float4* op = (float4*)(outs + ((size_t)b*TT + seg*64 + row)*NTAG + tg*8);
    op[0] = make_float4(t0.x + 0.5f*d0.x, t0.y + 0.5f*d0.y, t0.z + 0.5f*d1.x, t0.w + 0.5f*d1.y);
    op[1] = make_float4(t1.x + 0.5f*d2.x, t1.y + 0.5f*d2.y, t1.z + 0.5f*d3.x, t1.w + 0.5f*d3.y);
}

// ---------------- launch: proto forked onto side stream, overlapped with gemm ----------------
extern "C" void kernel_launch(void* const* d_in, const int* in_sizes, int n_in,
                              void* d_out, int out_size){
    const float* test_reps = (const float*)d_in[0];
    const float* support   = (const float*)d_in[1];
    const float* tgt       = (const float*)d_in[4];
    float* out_scores = (float*)d_out;                                  // (B,T,NT)
    float* out_proto  = (float*)d_out + (size_t)BB*TT*NTAG;             // (B,NT,D)

    static cudaStream_t s2 = 0;
    static cudaEvent_t evA = 0, evB = 0;
    static int tried = 0;
    if (!tried){
        tried = 1;
        cudaStream_t ts;
        if (cudaStreamCreateWithFlags(&ts, cudaStreamNonBlocking) == cudaSuccess){
            cudaEvent_t ea, eb;
            if (cudaEventCreateWithFlags(&ea, cudaEventDisableTiming) == cudaSuccess &&
                cudaEventCreateWithFlags(&eb, cudaEventDisableTiming) == cudaSuccess){
                s2 = ts; evA = ea; evB = eb;
            }
        }
    }

    k_f1<<<NMEAN + BB, 256>>>(test_reps, tgt);
    if (s2){
        cudaEventRecord(evA, 0);
        cudaStreamWaitEvent(s2, evA, 0);
        k_proto<<<dim3(BB, NTAG), 256, 0, s2>>>(support, out_proto);
        cudaEventRecord(evB, s2);
        k_gemm<<<dim3(CH, BB), 256, GEMM_SMEM>>>(support);
        cudaStreamWaitEvent(0, evB, 0);
    } else {
        k_proto<<<dim3(BB, NTAG), 256>>>(support, out_proto);
        k_gemm<<<dim3(CH, BB), 256, GEMM_SMEM>>>(support);
    }
    k_final<<<dim3(BB, 2), 256>>>(tgt, out_proto, out_scores);
}

// round 16
// speedup vs baseline: 1.3927x; 1.3927x over previous
#include <cuda_runtime.h>
#include <cuda_bf16.h>
#include <cstdint>

#define BB 32
#define KKS 10
#define TT 128
#define LLS 128
#define DD 1024
#define NTAG 32
#define SS (KKS*LLS)     // 1280
#define CH 20            // chunks of 64 support rows
#define CROWS 64

typedef unsigned long long ull;

// ---- dynamic smem layout for gemm (1024-aligned tiles, 48KB exactly) ----
#define OFF_AHI   0
#define OFF_ALO   16384
#define OFF_BHI   32768
#define OFF_BLO   40960
#define GEMM_SMEM 49152

#define NMEAN  4096

// ---------------- scratch (device globals; no allocation) ----------------
__device__ float  g_test_mean[BB*TT*DD];       // (B,T,D) fp32 16 MB
__device__ uint4  g_ahi[BB*TT*DD/8];           // test_mean hi bf16
__device__ uint4  g_alo[BB*TT*DD/8];           // test_mean lo bf16
__device__ int    g_list[BB*NTAG*256];
__device__ int    g_cnt[BB*NTAG];
__device__ float2 g_cmin[BB*TT*CH];

// ---------------- helpers ----------------
__device__ __forceinline__ uint32_t smem_u32(const void* p){
    uint32_t a;
    asm("{ .reg .u64 t; cvta.to.shared.u64 t, %1; cvt.u32.u64 %0, t; }" : "=r"(a) : "l"(p));
    return a;
}
__device__ __forceinline__ float4 add4(float4 a, float4 b){
    return make_float4(a.x+b.x, a.y+b.y, a.z+b.z, a.w+b.w);
}
__device__ __forceinline__ void bf16_split4(float4 v, uint32_t& h01, uint32_t& h23,
                                            uint32_t& l01, uint32_t& l23){
    asm("cvt.rn.bf16x2.f32 %0, %1, %2;" : "=r"(h01) : "f"(v.y), "f"(v.x));
    asm("cvt.rn.bf16x2.f32 %0, %1, %2;" : "=r"(h23) : "f"(v.w), "f"(v.z));
    float hx = __uint_as_float(h01<<16), hy = __uint_as_float(h01 & 0xffff0000u);
    float hz = __uint_as_float(h23<<16), hw = __uint_as_float(h23 & 0xffff0000u);
    asm("cvt.rn.bf16x2.f32 %0, %1, %2;" : "=r"(l01) : "f"(v.y-hy), "f"(v.x-hx));
    asm("cvt.rn.bf16x2.f32 %0, %1, %2;" : "=r"(l23) : "f"(v.w-hw), "f"(v.z-hz));
}
__device__ __forceinline__ void ldm_x4(uint32_t r[4], uint32_t addr){
    asm volatile("ldmatrix.sync.aligned.m8n8.x4.shared.b16 {%0,%1,%2,%3}, [%4];"
        : "=r"(r[0]),"=r"(r[1]),"=r"(r[2]),"=r"(r[3]) : "r"(addr));
}
__device__ __forceinline__ void mma_bf16(float c[4], const uint32_t a[4],
                                         uint32_t b0, uint32_t b1){
    asm volatile("mma.sync.aligned.m16n8k16.row.col.f32.bf16.bf16.f32 "
        "{%0,%1,%2,%3}, {%4,%5,%6,%7}, {%8,%9}, {%0,%1,%2,%3};"
        : "+f"(c[0]),"+f"(c[1]),"+f"(c[2]),"+f"(c[3])
        : "r"(a[0]),"r"(a[1]),"r"(a[2]),"r"(a[3]), "r"(b0),"r"(b1));
}
__device__ __forceinline__ uint32_t sw128(uint32_t off){ return off ^ ((off>>3)&0x70); }

// ================= k_mean: test_mean fp32 + bf16 hi/lo (R14 f1 mean path) =================
__global__ __launch_bounds__(256,4) void k_mean(const float* __restrict__ x){
    const int gx = blockIdx.x, tid = threadIdx.x;
    int idx = gx*256 + tid;
    int b   = idx / (TT*DD/4);
    int rem = idx - b*(TT*DD/4);
    const float4* p = (const float4*)x + (size_t)b*KKS*(TT*DD/4) + rem;
    float4 v[KKS];
#pragma unroll
    for (int k=0;k<KKS;k++) v[k] = p[(size_t)k*(TT*DD/4)];
    float4 s0 = add4(v[0], v[1]);
    float4 s1 = add4(v[2], v[3]);
    float4 s2 = add4(v[4], v[5]);
    float4 s3 = add4(v[6], v[7]);
    float4 s4 = add4(v[8], v[9]);
    float4 a  = add4(add4(add4(s0,s1), add4(s2,s3)), s4);
    const float s = 1.0f/(float)KKS;
    a.x*=s; a.y*=s; a.z*=s; a.w*=s;
    ((float4*)g_test_mean)[idx] = a;
    uint32_t h01,h23,l01,l23;
    bf16_split4(a, h01,h23,l01,l23);
    ((uint2*)g_ahi)[idx] = make_uint2(h01,h23);
    ((uint2*)g_alo)[idx] = make_uint2(l01,l23);
}

// ================= k_labels: labels + per-tag index lists (R14 f1 labels path) =================
__global__ __launch_bounds__(256) void k_labels(const float* __restrict__ tgt){
    __shared__ int lab[SS];
    int b = blockIdx.x, tid = threadIdx.x;
    for (int s = tid; s < SS; s += 256){
        const float* row = tgt + ((size_t)b*SS + s)*NTAG;
        float bv = row[0]; int bi = 0;
#pragma unroll
        for (int n=1;n<NTAG;n++){ float v=row[n]; if (v>bv){bv=v;bi=n;} }
        lab[s] = bi;
    }
    __syncthreads();
    int w = tid >> 5, lane = tid & 31;
    for (int n = w; n < NTAG; n += 8){
        int c = 0;
        int* lst = g_list + ((size_t)b*NTAG + n)*256;
        for (int s0 = 0; s0 < SS; s0 += 32){
            int s = s0 + lane;
            bool m = (lab[s] == n);
            unsigned bal = __ballot_sync(0xffffffffu, m);
            if (m && c + __popc(bal & ((1u<<lane)-1u)) < 256)
                lst[c + __popc(bal & ((1u<<lane)-1u))] = s;
            c += __popc(bal);
        }
        if (lane == 0) g_cnt[b*NTAG + n] = (c < 256) ? c : 256;
    }
}

// ---------------- prototypes: gather-sum / (count+1e-4), 8-wide MLP ----------------
__global__ __launch_bounds__(256) void k_proto(const float* __restrict__ sup,
                                               float* __restrict__ proto){
    int b = blockIdx.x, n = blockIdx.y, tid = threadIdx.x;
    __shared__ int sl[256];
    int cnt = g_cnt[b*NTAG + n];
    const int* lst = g_list + ((size_t)b*NTAG + n)*256;
    sl[tid] = (tid < cnt) ? lst[tid] : 0;
    __syncthreads();
    float4 acc = make_float4(0.f,0.f,0.f,0.f);
    const float4* base = (const float4*)(sup + (size_t)b*SS*DD) + tid;
    int jj = 0;
    for (; jj+8 <= cnt; jj += 8){
        float4 v[8];
#pragma unroll
        for (int q=0;q<8;q++) v[q] = base[(size_t)sl[jj+q]*(DD/4)];
        float4 p0 = add4(v[0],v[1]), p1 = add4(v[2],v[3]);
        float4 p2 = add4(v[4],v[5]), p3 = add4(v[6],v[7]);
        acc = add4(acc, add4(add4(p0,p1), add4(p2,p3)));
    }
    for (; jj < cnt; jj++)
        acc = add4(acc, base[(size_t)sl[jj]*(DD/4)]);
    float inv = 1.0f/((float)cnt + 1e-4f);
    acc.x*=inv; acc.y*=inv; acc.z*=inv; acc.w*=inv;
    ((float4*)(proto + ((size_t)b*NTAG + n)*DD))[tid] = acc;
}

// ---------------- HMMA bf16x3 GEMM (128 x 64 x 1024) + argmin (R14 exact) ----------------
__global__ __launch_bounds__(256,2) void k_gemm(const float* __restrict__ sup){
    extern __shared__ char smem[];
    const uint32_t sb = smem_u32(smem);
    const int ch = blockIdx.x, b = blockIdx.y;
    const int tid = threadIdx.x;
    const int lane = tid & 31, wid = tid >> 5;
    const int warp_m = wid & 3, warp_n = wid >> 2;

    const uint4*  A4h = g_ahi + (size_t)b*(TT*DD/8);
    const uint4*  A4l = g_alo + (size_t)b*(TT*DD/8);
    const float4* B4  = (const float4*)(sup + ((size_t)b*SS + (size_t)ch*CROWS)*DD);

    int amq[4], ajq[4], brq[4], bcq[4];
    uint32_t asw[4], bsw[4];
#pragma unroll
    for (int q=0;q<4;q++){
        int jj = tid + q*256;
        amq[q] = jj >> 3;  ajq[q] = jj & 7;
        asw[q] = sw128((uint32_t)(amq[q]*128 + ajq[q]*16));
        brq[q] = jj >> 4;  bcq[q] = jj & 15;
        bsw[q] = sw128((uint32_t)(brq[q]*128 + bcq[q]*8));
    }

    float acc[2][4][4];
#pragma unroll
    for (int mt=0;mt<2;mt++)
#pragma unroll
        for (int nn=0;nn<4;nn++)
#pragma unroll
            for (int e=0;e<4;e++) acc[mt][nn][e]=0.f;
    float nrm[4] = {0.f,0.f,0.f,0.f};

    const int a_row = (lane & 15);
    const int a_kb  = (lane >> 4) * 16;
    const int b_row = (lane & 7) + ((lane >> 4) << 3);
    const int b_kb  = ((lane >> 3) & 1) * 16;

    for (int kt = 0; kt < 16; kt++){
        __syncthreads();
        uint4 rAh[4], rAl[4]; float4 rB[4];
#pragma unroll
        for (int q=0;q<4;q++){
            rAh[q] = A4h[amq[q]*128 + kt*8 + ajq[q]];
            rAl[q] = A4l[amq[q]*128 + kt*8 + ajq[q]];
            rB[q]  = B4[(size_t)brq[q]*256 + kt*16 + bcq[q]];
        }
#pragma unroll
        for (int q=0;q<4;q++){
            *(uint4*)(smem + OFF_AHI + asw[q]) = rAh[q];
            *(uint4*)(smem + OFF_ALO + asw[q]) = rAl[q];
            float4 v = rB[q];
            nrm[q] += v.x*v.x + v.y*v.y + v.z*v.z + v.w*v.w;
            uint32_t h01,h23,l01,l23;
            bf16_split4(v, h01,h23,l01,l23);
            *(uint2*)(smem + OFF_BHI + bsw[q]) = make_uint2(h01,h23);
            *(uint2*)(smem + OFF_BLO + bsw[q]) = make_uint2(l01,l23);
        }
        __syncthreads();
#pragma unroll
        for (int ks=0; ks<4; ks++){
            uint32_t ah[2][4], al[2][4], bh[2][4], bl[2][4];
#pragma unroll
            for (int mt=0;mt<2;mt++){
                uint32_t off = sw128((uint32_t)((warp_m*32 + mt*16 + a_row)*128 + ks*32 + a_kb));
                ldm_x4(ah[mt], sb + OFF_AHI + off);
                ldm_x4(al[mt], sb + OFF_ALO + off);
            }
#pragma unroll
            for (int p=0;p<2;p++){
                uint32_t off = sw128((uint32_t)((warp_n*32 + p*16 + b_row)*128 + ks*32 + b_kb));
                ldm_x4(bh[p], sb + OFF_BHI + off);
                ldm_x4(bl[p], sb + OFF_BLO + off);
            }
#pragma unroll
            for (int mt=0;mt<2;mt++)
#pragma unroll
                for (int nn=0;nn<4;nn++){
                    const int p = nn>>1, h = (nn&1)*2;
                    mma_bf16(acc[mt][nn], ah[mt], bh[p][h], bh[p][h+1]);
                    mma_bf16(acc[mt][nn], ah[mt], bl[p][h], bl[p][h+1]);
                    mma_bf16(acc[mt][nn], al[mt], bh[p][h], bh[p][h+1]);
                }
        }
    }
    __syncthreads();

    float*  snorm_s = (float*)(smem);
    float2* rmin_s  = (float2*)(smem + 256);

#pragma unroll
    for (int q=0;q<4;q++){
        float v = nrm[q];
        v += __shfl_xor_sync(0xffffffffu, v, 8, 16);
        v += __shfl_xor_sync(0xffffffffu, v, 4, 16);
        v += __shfl_xor_sync(0xffffffffu, v, 2, 16);
        v += __shfl_xor_sync(0xffffffffu, v, 1, 16);
        if ((tid & 15) == 0) snorm_s[(tid>>4) + q*16] = v;
    }
    __syncthreads();

#pragma unroll
    for (int mt=0;mt<2;mt++){
#pragma unroll
        for (int rh=0;rh<2;rh++){
            int m = warp_m*32 + mt*16 + (lane>>2) + rh*8;
            float bv = 3.4e38f; int bi = 1<<30;
#pragma unroll
            for (int nn=0;nn<4;nn++){
#pragma unroll
                for (int e=0;e<2;e++){
                    int n = warp_n*32 + nn*8 + 2*(lane&3) + e;
                    float s = snorm_s[n] - 2.f*acc[mt][nn][rh*2+e];
                    if (s < bv || (s==bv && n < bi)){ bv=s; bi=n; }
                }
            }
#pragma unroll
            for (int o=2;o;o>>=1){
                float ov = __shfl_down_sync(0xffffffffu, bv, o, 4);
                int   oi = __shfl_down_sync(0xffffffffu, bi, o, 4);
                if (ov < bv || (ov==bv && oi<bi)){ bv=ov; bi=oi; }
            }
            if ((lane&3)==0) rmin_s[m*2 + warp_n] = make_float2(bv, __int_as_float(bi));
        }
    }
    __syncthreads();
    if (tid < TT){
        float2 v0 = rmin_s[tid*2 + 0], v1 = rmin_s[tid*2 + 1];
        float bv = v0.x; int bi = __float_as_int(v0.y);
        if (v1.x < bv){ bv = v1.x; bi = __float_as_int(v1.y); }
        g_cmin[((size_t)b*TT + tid)*CH + ch] = make_float2(bv, __int_as_float(ch*CROWS + bi));
    }
}

// ------- k_final: grid (B,4); 32 rows x 32 tags; 2 FFMA2 per A-LDS (R14 exact) -------
__global__ __launch_bounds__(256) void k_final(const float* __restrict__ tgt,
                                               const float* __restrict__ proto,
                                               float* __restrict__ outs){
    __shared__ float As[64][33];
    __shared__ float Bs[64][40];
    __shared__ int   snn[32];
    int b = blockIdx.x, seg = blockIdx.y, tid = threadIdx.x;
    const int row = tid & 31, tq = tid >> 5;

    if (tid < 32){
        const float2* e = &g_cmin[((size_t)b*TT + seg*32 + tid)*CH];
        float2 v0 = e[0];
        float bv = v0.x; int bi = __float_as_int(v0.y);
#pragma unroll
        for (int c=1;c<CH;c++){
            float2 v = e[c];
            if (v.x < bv){ bv = v.x; bi = __float_as_int(v.y); }
        }
        snn[tid] = bi;
    }

    const float* Ab = g_test_mean + ((size_t)b*TT + seg*32)*DD;
    const float* Pb = proto + (size_t)b*NTAG*DD;
    const int lr = tid & 31, lk = tid >> 5;

    float4 va0 = *(const float4*)(Ab + (size_t)lr*DD + lk*4);
    float4 va1 = *(const float4*)(Ab + (size_t)lr*DD + (lk+8)*4);
    float4 vb0 = *(const float4*)(Pb + (size_t)lr*DD + lk*4);
    float4 vb1 = *(const float4*)(Pb + (size_t)lr*DD + (lk+8)*4);

    ull acc0 = 0ull, acc1 = 0ull;
    for (int kt=0; kt<16; kt++){
        __syncthreads();
        As[lk*4+0][lr]=va0.x; As[lk*4+1][lr]=va0.y; As[lk*4+2][lr]=va0.z; As[lk*4+3][lr]=va0.w;
        As[(lk+8)*4+0][lr]=va1.x; As[(lk+8)*4+1][lr]=va1.y; As[(lk+8)*4+2][lr]=va1.z; As[(lk+8)*4+3][lr]=va1.w;
        Bs[lk*4+0][lr]=vb0.x; Bs[lk*4+1][lr]=vb0.y; Bs[lk*4+2][lr]=vb0.z; Bs[lk*4+3][lr]=vb0.w;
        Bs[(lk+8)*4+0][lr]=vb1.x; Bs[(lk+8)*4+1][lr]=vb1.y; Bs[(lk+8)*4+2][lr]=vb1.z; Bs[(lk+8)*4+3][lr]=vb1.w;
        __syncthreads();
        if (kt < 15){
            const int off = (kt+1)*64;
            va0 = *(const float4*)(Ab + (size_t)lr*DD + off + lk*4);
            va1 = *(const float4*)(Ab + (size_t)lr*DD + off + (lk+8)*4);
            vb0 = *(const float4*)(Pb + (size_t)lr*DD + off + lk*4);
            vb1 = *(const float4*)(Pb + (size_t)lr*DD + off + (lk+8)*4);
        }
#pragma unroll
        for (int kk=0;kk<64;kk++){
            float a = As[kk][row];
            const ull* bp = (const ull*)&Bs[kk][tq*4];
            ull b0 = bp[0], b1 = bp[1];
            ull aa;
            asm("mov.b64 %0, {%1, %1};" : "=l"(aa) : "f"(a));
            asm("fma.rn.f32x2 %0, %1, %2, %0;" : "+l"(acc0) : "l"(aa), "l"(b0));
            asm("fma.rn.f32x2 %0, %1, %2, %0;" : "+l"(acc1) : "l"(aa), "l"(b1));
        }
    }
    __syncthreads();

    int nn = snn[row];
    float2 d0 = *(float2*)&acc0, d1 = *(float2*)&acc1;
    float4 t = *(const float4*)(tgt + ((size_t)b*SS + nn)*NTAG + tq*4);
    *(float4*)(outs + ((size_t)b*TT + seg*32 + row)*NTAG + tq*4) =
        make_float4(t.x + 0.5f*d0.x, t.y + 0.5f*d0.y, t.z + 0.5f*d1.x, t.w + 0.5f*d1.y);
}

// ---------------- launch: labels+proto on side stream, overlapped with mean ----------------
extern "C" void kernel_launch(void* const* d_in, const int* in_sizes, int n_in,
                              void* d_out, int out_size){
    const float* test_reps = (const float*)d_in[0];
    const float* support   = (const float*)d_in[1];
    const float* tgt       = (const float*)d_in[4];
    float* out_scores = (float*)d_out;                                  // (B,T,NT)
    float* out_proto  = (float*)d_out + (size_t)BB*TT*NTAG;             // (B,NT,D)

    static cudaStream_t s2 = 0;
    static cudaEvent_t evA = 0, evB = 0;
    static int tried = 0;
    if (!tried){
        tried = 1;
        cudaStream_t ts;
        if (cudaStreamCreateWithFlags(&ts, cudaStreamNonBlocking) == cudaSuccess){
            cudaEvent_t ea, eb;
            if (cudaEventCreateWithFlags(&ea, cudaEventDisableTiming) == cudaSuccess &&
                cudaEventCreateWithFlags(&eb, cudaEventDisableTiming) == cudaSuccess){
                s2 = ts; evA = ea; evB = eb;
            }
        }
    }

    if (s2){
        // fork s2 from the capture-origin stream, run labels->proto there
        cudaEventRecord(evA, 0);
        cudaStreamWaitEvent(s2, evA, 0);
        k_labels<<<BB, 256, 0, s2>>>(tgt);
        k_proto <<<dim3(BB, NTAG), 256, 0, s2>>>(support, out_proto);
        cudaEventRecord(evB, s2);
        // main stream: mean -> gemm (independent of labels/proto)
        k_mean<<<NMEAN, 256>>>(test_reps);
        k_gemm<<<dim3(CH, BB), 256, GEMM_SMEM>>>(support);
        cudaStreamWaitEvent(0, evB, 0);
    } else {
        k_mean  <<<NMEAN, 256>>>(test_reps);
        k_labels<<<BB, 256>>>(tgt);
        k_proto <<<dim3(BB, NTAG), 256>>>(support, out_proto);
        k_gemm  <<<dim3(CH, BB), 256, GEMM_SMEM>>>(support);
    }
    k_final<<<dim3(BB, 4), 256>>>(tgt, out_proto, out_scores);
}